// round 13
// baseline (speedup 1.0000x reference)
#include <cuda_runtime.h>

// DWTExtractor: 2-level Haar DWT + bilinear 2x upsample of level-2 details.
// Input:  (32, 1, 1024, 1024) fp32 -> Output: (32, 6, 512, 512) fp32
//          [cH1, cV1, cD1, up(cH2), up(cV2), up(cD2)]
//
// 32x32 output tile per block, 384 threads, both phases single-pass:
//   Merged phase (tid < 324): one level-2 cell per thread over the 18x18
//     grid (incl. 1-halo, clamped == jax resize weight renormalization).
//     4 x LDG.128 per cell (lanes -> consecutive float4 columns), level-2
//     coeffs -> smem; central 16x16 cells also emit the 2x2 level-1 detail
//     block -> gmem (float2 streaming stores).
//   (one __syncthreads)
//   Part 3: 768 channel-items (ch, y, xq) over 384 threads = exactly 2 per
//     thread; each item = 4 horizontal outputs of one channel via scalar LDS
//     (vector-LDS variant measured slower in R10), float4 streaming store.

#define TS    32
#define H2_T  18
#define H2_S  19

__global__ __launch_bounds__(384, 4)
void dwt_fused_kernel(const float* __restrict__ in, float* __restrict__ out)
{
    __shared__ float sH[H2_T * H2_S];
    __shared__ float sV[H2_T * H2_S];
    __shared__ float sD[H2_T * H2_S];

    const int b   = blockIdx.z;
    const int oy0 = blockIdx.y * TS;
    const int ox0 = blockIdx.x * TS;
    const int tid = threadIdx.x;

    const float* __restrict__ inb  = in  + (size_t)b * 1024 * 1024;
    float* __restrict__       outb = out + (size_t)b * 6 * 512 * 512;

    // ---- Merged phase: level-2 (18x18 w/ halo) + level-1 (central 16x16) ----
    const int r0g = oy0 >> 1;   // level-2 tile origin on the 256-grid
    const int c0g = ox0 >> 1;
    if (tid < H2_T * H2_T) {
        const int lr = tid / H2_T;
        const int lc = tid - lr * H2_T;
        const int rr = r0g - 1 + lr;
        const int cc = c0g - 1 + lc;
        const int r = min(max(rr, 0), 255);   // clamp only bites on halo cells
        const int c = min(max(cc, 0), 255);

        const float4 v0 = *((const float4*)(inb + (size_t)(4 * r    ) * 1024) + c);
        const float4 v1 = *((const float4*)(inb + (size_t)(4 * r + 1) * 1024) + c);
        const float4 v2 = *((const float4*)(inb + (size_t)(4 * r + 2) * 1024) + c);
        const float4 v3 = *((const float4*)(inb + (size_t)(4 * r + 3) * 1024) + c);

        // per-row horizontal sums/diffs
        const float s0l = v0.x + v0.y, d0l = v0.x - v0.y;
        const float s0r = v0.z + v0.w, d0r = v0.z - v0.w;
        const float s1l = v1.x + v1.y, d1l = v1.x - v1.y;
        const float s1r = v1.z + v1.w, d1r = v1.z - v1.w;
        const float s2l = v2.x + v2.y, d2l = v2.x - v2.y;
        const float s2r = v2.z + v2.w, d2r = v2.z - v2.w;
        const float s3l = v3.x + v3.y, d3l = v3.x - v3.y;
        const float s3r = v3.z + v3.w, d3r = v3.z - v3.w;

        // 2*cA1 quad
        const float a00 = s0l + s1l, a01 = s0r + s1r;
        const float a10 = s2l + s3l, a11 = s2r + s3r;

        // level-2 coeffs: 0.5 (haar) * 0.5 (cA1 factor folded) = 0.25
        sH[lr * H2_S + lc] = (a00 - a01 + a10 - a11) * 0.25f;
        sV[lr * H2_S + lc] = (a00 + a01 - a10 - a11) * 0.25f;
        sD[lr * H2_S + lc] = (a00 - a01 - a10 + a11) * 0.25f;

        // central cells: emit the 2x2 level-1 detail block (rows 2rr, 2rr+1;
        // cols 2cc, 2cc+1 on the 512-grid). lr,lc in [1,16] <=> unclamped.
        if ((unsigned)(lr - 1) < 16u && (unsigned)(lc - 1) < 16u) {
            const float2 hT = make_float2((d0l + d1l) * 0.5f, (d0r + d1r) * 0.5f);
            const float2 vT = make_float2((s0l - s1l) * 0.5f, (s0r - s1r) * 0.5f);
            const float2 dT = make_float2((d0l - d1l) * 0.5f, (d0r - d1r) * 0.5f);
            const float2 hB = make_float2((d2l + d3l) * 0.5f, (d2r + d3r) * 0.5f);
            const float2 vB = make_float2((s2l - s3l) * 0.5f, (s2r - s3r) * 0.5f);
            const float2 dB = make_float2((d2l - d3l) * 0.5f, (d2r - d3r) * 0.5f);

            const size_t oT = (size_t)(2 * rr) * 256 + cc;   // float2 index
            const size_t oB = oT + 256;                      // next row
            float2* o2 = (float2*)outb;
            __stcs(o2 + 0 * 131072 + oT, hT);
            __stcs(o2 + 0 * 131072 + oB, hB);
            __stcs(o2 + 1 * 131072 + oT, vT);
            __stcs(o2 + 1 * 131072 + oB, vB);
            __stcs(o2 + 2 * 131072 + oT, dT);
            __stcs(o2 + 2 * 131072 + oB, dB);
        }
    }

    __syncthreads();

    // ---- Part 3: half-pixel bilinear 2x ----
    // 768 channel-items over 384 threads, 2 per thread.
    // item: ch in {0,1,2}, y in 0..31, xq in 0..7 (4 horizontal outputs).
    // out[2k] = 0.25*v[k-1]+0.75*v[k],  out[2k+1] = 0.75*v[k]+0.25*v[k+1]
    #pragma unroll
    for (int it = 0; it < 2; it++) {
        const int idx = tid + it * 384;      // 0..767
        const int ch  = idx >> 8;            // 0..2
        const int rem = idx & 255;
        const int y   = rem >> 3;            // 0..31
        const int xq  = rem & 7;             // group of 4 cols

        const int ky  = (y >> 1) + 1;        // local level-2 row of k
        const int ry0 = (y & 1) ? ky     : ky - 1;
        const int ry1 = (y & 1) ? ky + 1 : ky;
        const float wy0 = (y & 1) ? 0.75f : 0.25f;
        const float wy1 = 1.0f - wy0;

        const int cb = 2 * xq;               // local level-2 cols cb..cb+3
        const int A0 = ry0 * H2_S + cb;
        const int A1 = ry1 * H2_S + cb;

        const float* s = (ch == 0) ? sH : (ch == 1) ? sV : sD;
        const float m0 = wy0 * s[A0    ] + wy1 * s[A1    ];
        const float m1 = wy0 * s[A0 + 1] + wy1 * s[A1 + 1];
        const float m2 = wy0 * s[A0 + 2] + wy1 * s[A1 + 2];
        const float m3 = wy0 * s[A0 + 3] + wy1 * s[A1 + 3];

        const float4 rv = make_float4(0.25f * m0 + 0.75f * m1,
                                      0.75f * m1 + 0.25f * m2,
                                      0.25f * m1 + 0.75f * m2,
                                      0.75f * m2 + 0.25f * m3);

        const size_t o4 = ((size_t)(oy0 + y) * 512 + ox0 + 4 * xq) >> 2;
        __stcs((float4*)outb + (size_t)(3 + ch) * 65536 + o4, rv);
    }
}

extern "C" void kernel_launch(void* const* d_in, const int* in_sizes, int n_in,
                              void* d_out, int out_size)
{
    const float* x = (const float*)d_in[0];
    float* out = (float*)d_out;
    dim3 grid(512 / TS, 512 / TS, 32);   // (16, 16, 32) = 8192 blocks
    dwt_fused_kernel<<<grid, 384>>>(x, out);
}